// round 3
// baseline (speedup 1.0000x reference)
#include <cuda_runtime.h>
#include <cuda_bf16.h>
#include <math.h>

#define Bc 64
#define Tt 197
#define Dd 768
#define Hh 12
#define DKk 64
#define Mrows (Bc * Tt)   // 12608

typedef unsigned long long u64;

__device__ __forceinline__ u64 pk2(float lo, float hi) {
    u64 r; asm("mov.b64 %0,{%1,%2};" : "=l"(r) : "f"(lo), "f"(hi)); return r;
}
__device__ __forceinline__ float2 upk2(u64 v) {
    float2 f; asm("mov.b64 {%0,%1},%2;" : "=f"(f.x), "=f"(f.y) : "l"(v)); return f;
}
__device__ __forceinline__ void ffma2(u64 &c, u64 a, u64 b) {
    asm("fma.rn.f32x2 %0,%1,%2,%0;" : "+l"(c) : "l"(a), "l"(b));
}

// Scratch
__device__ float g_q[Bc * Hh * Tt * DKk];
__device__ float g_k[Bc * Hh * Tt * DKk];
__device__ float g_v[Bc * Hh * Tt * DKk];
__device__ float g_ctx[Bc * Tt * Dd];

// ---------------------------------------------------------------------------
// GEMM core: out = A[M,768] @ W[768,768] + bias.
// Dup-pair W smem (zero pack MOVs in inner loop), register prefetch, KT=16.
// mode 0: head-split write [B,H,T,DK]; mode 1: row-major [M,768]
// ---------------------------------------------------------------------------
#define KT 16

__device__ __forceinline__ void gemm_core(
    const float* __restrict__ A, const float* __restrict__ W,
    const float* __restrict__ bias, float* __restrict__ out, int mode,
    float* As /*[KT*128]*/, float* Wd /*[KT*256]*/)
{
    const int tid = threadIdx.x;
    const int tx = tid & 15;
    const int ty = tid >> 4;
    const int m0 = blockIdx.y * 128;
    const int n0 = blockIdx.x * 128;

    u64 c2[4][8];
#pragma unroll
    for (int i = 0; i < 4; i++)
#pragma unroll
        for (int j = 0; j < 8; j++) c2[i][j] = 0ull;

    const int ar = tid >> 1;      // A row 0..127
    const int ah = tid & 1;       // A k-half
    const int wk = tid >> 5;      // W k-row 0..7 (and +8)
    const int wc = tid & 31;      // W col base

    float4 a0, a1;
    float wv0[4], wv1[4];

    // prefetch tile k0=0
    {
        a0 = make_float4(0.f, 0.f, 0.f, 0.f); a1 = a0;
        if (m0 + ar < Mrows) {
            const float* Ap = A + (size_t)(m0 + ar) * Dd + ah * 8;
            a0 = *(const float4*)Ap;
            a1 = *(const float4*)(Ap + 4);
        }
        const float* Wp = W + (size_t)wk * Dd + n0 + wc;
#pragma unroll
        for (int i = 0; i < 4; i++) {
            wv0[i] = Wp[32 * i];
            wv1[i] = Wp[8 * Dd + 32 * i];
        }
    }

    for (int k0 = 0; k0 < Dd; k0 += KT) {
        __syncthreads();
        // store prefetched tile
        As[(ah * 8 + 0) * 128 + ar] = a0.x; As[(ah * 8 + 1) * 128 + ar] = a0.y;
        As[(ah * 8 + 2) * 128 + ar] = a0.z; As[(ah * 8 + 3) * 128 + ar] = a0.w;
        As[(ah * 8 + 4) * 128 + ar] = a1.x; As[(ah * 8 + 5) * 128 + ar] = a1.y;
        As[(ah * 8 + 6) * 128 + ar] = a1.z; As[(ah * 8 + 7) * 128 + ar] = a1.w;
#pragma unroll
        for (int i = 0; i < 4; i++) {
            *(float2*)&Wd[wk * 256 + (wc + 32 * i) * 2]       = make_float2(wv0[i], wv0[i]);
            *(float2*)&Wd[(wk + 8) * 256 + (wc + 32 * i) * 2] = make_float2(wv1[i], wv1[i]);
        }
        __syncthreads();

        // prefetch next
        if (k0 + KT < Dd) {
            a0 = make_float4(0.f, 0.f, 0.f, 0.f); a1 = a0;
            if (m0 + ar < Mrows) {
                const float* Ap = A + (size_t)(m0 + ar) * Dd + (k0 + KT) + ah * 8;
                a0 = *(const float4*)Ap;
                a1 = *(const float4*)(Ap + 4);
            }
            const float* Wp = W + (size_t)(k0 + KT + wk) * Dd + n0 + wc;
#pragma unroll
            for (int i = 0; i < 4; i++) {
                wv0[i] = Wp[32 * i];
                wv1[i] = Wp[8 * Dd + 32 * i];
            }
        }

#pragma unroll
        for (int kk = 0; kk < KT; kk++) {
            const float* Ak = As + kk * 128;
            const float* Wr = Wd + kk * 256;
            u64 ap[4];
            ap[0] = *(const u64*)&Ak[ty * 4];
            ap[1] = *(const u64*)&Ak[ty * 4 + 2];
            ap[2] = *(const u64*)&Ak[64 + ty * 4];
            ap[3] = *(const u64*)&Ak[64 + ty * 4 + 2];
            u64 bd[8];
#pragma unroll
            for (int j = 0; j < 4; j++) {
                bd[j]     = *(const u64*)&Wr[(tx * 4 + j) * 2];
                bd[4 + j] = *(const u64*)&Wr[(64 + tx * 4 + j) * 2];
            }
#pragma unroll
            for (int i = 0; i < 4; i++)
#pragma unroll
                for (int j = 0; j < 8; j++) ffma2(c2[i][j], ap[i], bd[j]);
        }
    }

    // epilogue
#pragma unroll
    for (int i = 0; i < 4; i++) {
        int rbase = m0 + ((i < 2) ? (ty * 4 + i * 2) : (64 + ty * 4 + (i - 2) * 2));
#pragma unroll
        for (int j = 0; j < 8; j++) {
            int cidx = n0 + ((j < 4) ? (tx * 4 + j) : (64 + tx * 4 + (j - 4)));
            float2 f = upk2(c2[i][j]);
            float bia = bias[cidx];
            f.x += bia; f.y += bia;
#pragma unroll
            for (int s = 0; s < 2; s++) {
                int r = rbase + s;
                if (r >= Mrows) continue;
                float v = s ? f.y : f.x;
                if (mode == 0) {
                    int bi = r / Tt, t = r - (r / Tt) * Tt;
                    int h = cidx >> 6, dk = cidx & 63;
                    out[(((size_t)(bi * Hh + h)) * Tt + t) * DKk + dk] = v;
                } else {
                    out[(size_t)r * Dd + cidx] = v;
                }
            }
        }
    }
}

// Fused QKV: blockIdx.z selects which projection
__global__ void __launch_bounds__(256, 2) qkv_kernel(
    const float* __restrict__ x,
    const float* __restrict__ Wq, const float* __restrict__ Wk2, const float* __restrict__ Wv,
    const float* __restrict__ bq, const float* __restrict__ bk2, const float* __restrict__ bv,
    float* __restrict__ q, float* __restrict__ k, float* __restrict__ v)
{
    __shared__ float As[KT * 128];
    __shared__ float Wd[KT * 256];
    int z = blockIdx.z;
    const float* W = (z == 0) ? Wq : (z == 1) ? Wk2 : Wv;
    const float* bia = (z == 0) ? bq : (z == 1) ? bk2 : bv;
    float* out = (z == 0) ? q : (z == 1) ? k : v;
    gemm_core(x, W, bia, out, 0, As, Wd);
}

__global__ void __launch_bounds__(256, 2) oproj_kernel(
    const float* __restrict__ ctx, const float* __restrict__ Wo,
    const float* __restrict__ bo, float* __restrict__ out)
{
    __shared__ float As[KT * 128];
    __shared__ float Wd[KT * 256];
    gemm_core(ctx, Wo, bo, out, 1, As, Wd);
}

// ---------------------------------------------------------------------------
// Attention v3: per (b,h) CTA, 384 threads (12 warps), 4 rows per warp-group.
// K/V smem layout: word = j*64 + ((c + 2j) & 63)  -> conflict-free LDS.64.
// P stored row-interleaved Pg[j][4] (one LDS.128 broadcast serves 4 rows).
// ---------------------------------------------------------------------------
#define ATTN_SMEM ((2 * Tt * 64 + 12 * 800) * 4)   // 139264 bytes

__global__ void __launch_bounds__(384) attn3_kernel(
    const float* __restrict__ Q, const float* __restrict__ K,
    const float* __restrict__ V, float* __restrict__ ctx)
{
    extern __shared__ float sm[];
    float* Ks = sm;
    float* Vs = sm + Tt * 64;
    const int tid  = threadIdx.x;
    const int lane = tid & 31;
    const int w    = tid >> 5;
    float* Pg = sm + 2 * Tt * 64 + w * 800;

    const int bh = blockIdx.x;
    const int b  = bh / Hh;
    const int h  = bh - b * Hh;

    const float* Kb = K + (size_t)bh * Tt * DKk;
    const float* Vb = V + (size_t)bh * Tt * DKk;
    const float* Qb = Q + (size_t)bh * Tt * DKk;

    // fill K/V with rotated-pair layout
    for (int e = tid; e < Tt * 32; e += 384) {
        int j = e >> 5, p = e & 31, c = 2 * p;
        int off = j * 64 + ((c + 2 * j) & 63);
        *(float2*)&Ks[off] = *(const float2*)&Kb[j * 64 + c];
        *(float2*)&Vs[off] = *(const float2*)&Vb[j * 64 + c];
    }
    __syncthreads();

    int jj[7], rot[7];
#pragma unroll
    for (int u = 0; u < 7; u++) {
        int j = lane + 32 * u;
        jj[u]  = (j > Tt - 1) ? (Tt - 1) : j;
        rot[u] = (2 * jj[u]) & 63;
    }
    const int myc = 2 * lane;

    for (int g = w; g < 50; g += 12) {
        const int r0 = g * 4;
        int rs[4];
#pragma unroll
        for (int s = 0; s < 4; s++) rs[s] = (r0 + s > Tt - 1) ? (Tt - 1) : (r0 + s);

        u64 acc[4][7];
#pragma unroll
        for (int s = 0; s < 4; s++)
#pragma unroll
            for (int u = 0; u < 7; u++) acc[s][u] = 0ull;

#pragma unroll
        for (int dc = 0; dc < 8; dc++) {
            u64 qp[4][4];
#pragma unroll
            for (int s = 0; s < 4; s++) {
                const float* qs = Qb + rs[s] * DKk + dc * 8;
                float4 qa = *(const float4*)qs;
                float4 qb = *(const float4*)(qs + 4);
                qp[s][0] = pk2(qa.x, qa.y); qp[s][1] = pk2(qa.z, qa.w);
                qp[s][2] = pk2(qb.x, qb.y); qp[s][3] = pk2(qb.z, qb.w);
            }
            const int c0 = dc * 8;
#pragma unroll
            for (int u = 0; u < 7; u++) {
                const float* kr = Ks + jj[u] * 64;
                u64 kp0 = *(const u64*)&kr[(c0 + 0 + rot[u]) & 63];
                u64 kp1 = *(const u64*)&kr[(c0 + 2 + rot[u]) & 63];
                u64 kp2 = *(const u64*)&kr[(c0 + 4 + rot[u]) & 63];
                u64 kp3 = *(const u64*)&kr[(c0 + 6 + rot[u]) & 63];
#pragma unroll
                for (int s = 0; s < 4; s++) {
                    ffma2(acc[s][u], qp[s][0], kp0);
                    ffma2(acc[s][u], qp[s][1], kp1);
                    ffma2(acc[s][u], qp[s][2], kp2);
                    ffma2(acc[s][u], qp[s][3], kp3);
                }
            }
        }

        // softmax per row
        float iv[4];
#pragma unroll
        for (int s = 0; s < 4; s++) {
            float sc[7];
            float mx = -1e30f;
#pragma unroll
            for (int u = 0; u < 7; u++) {
                float2 f = upk2(acc[s][u]);
                float val = floorf((f.x + f.y) * 0.125f);
                sc[u] = (lane + 32 * u < Tt) ? val : -1e30f;
                mx = fmaxf(mx, sc[u]);
            }
#pragma unroll
            for (int o = 16; o; o >>= 1) mx = fmaxf(mx, __shfl_xor_sync(0xffffffffu, mx, o));
            float sum = 0.f;
#pragma unroll
            for (int u = 0; u < 7; u++) {
                if (lane + 32 * u < Tt) {
                    float p = __expf(sc[u] - mx);
                    Pg[jj[u] * 4 + s] = p;
                    sum += p;
                }
            }
#pragma unroll
            for (int o = 16; o; o >>= 1) sum += __shfl_xor_sync(0xffffffffu, sum, o);
            iv[s] = 1.f / sum;
        }
        __syncwarp();

        // AV: lane owns d-pair (myc, myc+1)
        u64 a[4] = {0ull, 0ull, 0ull, 0ull};
        for (int j = 0; j < Tt - 1; j += 2) {
            u64 v0 = *(const u64*)&Vs[j * 64 + ((myc + 2 * j) & 63)];
            u64 v1 = *(const u64*)&Vs[(j + 1) * 64 + ((myc + 2 * j + 2) & 63)];
            float4 pa = *(const float4*)&Pg[j * 4];
            float4 pb = *(const float4*)&Pg[j * 4 + 4];
            ffma2(a[0], pk2(pa.x, pa.x), v0); ffma2(a[0], pk2(pb.x, pb.x), v1);
            ffma2(a[1], pk2(pa.y, pa.y), v0); ffma2(a[1], pk2(pb.y, pb.y), v1);
            ffma2(a[2], pk2(pa.z, pa.z), v0); ffma2(a[2], pk2(pb.z, pb.z), v1);
            ffma2(a[3], pk2(pa.w, pa.w), v0); ffma2(a[3], pk2(pb.w, pb.w), v1);
        }
        {   // tail j = 196
            int j = Tt - 1;
            u64 v0 = *(const u64*)&Vs[j * 64 + ((myc + 2 * j) & 63)];
            float4 pa = *(const float4*)&Pg[j * 4];
            ffma2(a[0], pk2(pa.x, pa.x), v0);
            ffma2(a[1], pk2(pa.y, pa.y), v0);
            ffma2(a[2], pk2(pa.z, pa.z), v0);
            ffma2(a[3], pk2(pa.w, pa.w), v0);
        }

#pragma unroll
        for (int s = 0; s < 4; s++) {
            float2 o = upk2(a[s]);
            o.x *= iv[s]; o.y *= iv[s];
            *(float2*)&ctx[((size_t)(b * Tt + rs[s])) * Dd + h * DKk + myc] = o;
        }
        __syncwarp();
    }
}

// ---------------------------------------------------------------------------
extern "C" void kernel_launch(void* const* d_in, const int* in_sizes, int n_in,
                              void* d_out, int out_size)
{
    const float* x  = (const float*)d_in[0];
    const float* Wq = (const float*)d_in[1];
    const float* bq = (const float*)d_in[2];
    const float* Wk = (const float*)d_in[3];
    const float* bk = (const float*)d_in[4];
    const float* Wv = (const float*)d_in[5];
    const float* bv = (const float*)d_in[6];
    const float* Wo = (const float*)d_in[7];
    const float* bo = (const float*)d_in[8];
    float* out = (float*)d_out;

    float *q, *k, *v, *ctx;
    cudaGetSymbolAddress((void**)&q,   g_q);
    cudaGetSymbolAddress((void**)&k,   g_k);
    cudaGetSymbolAddress((void**)&v,   g_v);
    cudaGetSymbolAddress((void**)&ctx, g_ctx);

    cudaFuncSetAttribute(attn3_kernel,
                         cudaFuncAttributeMaxDynamicSharedMemorySize, ATTN_SMEM);

    dim3 gridQKV(Dd / 128, (Mrows + 127) / 128, 3);   // 6 x 99 x 3
    qkv_kernel<<<gridQKV, 256>>>(x, Wq, Wk, Wv, bq, bk, bv, q, k, v);

    attn3_kernel<<<Bc * Hh, 384, ATTN_SMEM>>>(q, k, v, ctx);

    dim3 gridO(Dd / 128, (Mrows + 127) / 128, 1);
    oproj_kernel<<<gridO, 256>>>(ctx, Wo, bo, out);
}

// round 4
// speedup vs baseline: 1.6953x; 1.6953x over previous
#include <cuda_runtime.h>
#include <cuda_bf16.h>
#include <math.h>

#define Bc 64
#define Tt 197
#define Dd 768
#define Hh 12
#define DKk 64
#define Mrows (Bc * Tt)   // 12608

typedef unsigned long long u64;

__device__ __forceinline__ u64 pk2(float lo, float hi) {
    u64 r; asm("mov.b64 %0,{%1,%2};" : "=l"(r) : "f"(lo), "f"(hi)); return r;
}
__device__ __forceinline__ float2 upk2(u64 v) {
    float2 f; asm("mov.b64 {%0,%1},%2;" : "=f"(f.x), "=f"(f.y) : "l"(v)); return f;
}
__device__ __forceinline__ void ffma2(u64 &c, u64 a, u64 b) {
    asm("fma.rn.f32x2 %0,%1,%2,%0;" : "+l"(c) : "l"(a), "l"(b));
}

// Scratch
__device__ float g_q[Bc * Hh * Tt * DKk];
__device__ float g_k[Bc * Hh * Tt * DKk];
__device__ float g_v[Bc * Hh * Tt * DKk];
__device__ float g_ctx[Bc * Tt * Dd];

// ---------------------------------------------------------------------------
// GEMM core: out = A[M,768] @ W[768,768] + bias
// R2 smem layout (As[KT][128], Ws[KT][128]) + direct LDS.64 A-pairs +
// register prefetch of next tile. FMA2-bound inner loop.
// mode 0: head-split write [B,H,T,DK]; mode 1: row-major [M,768]
// ---------------------------------------------------------------------------
#define KT 16

__device__ __forceinline__ void gemm_core(
    const float* __restrict__ A, const float* __restrict__ W,
    const float* __restrict__ bias, float* __restrict__ out, int mode,
    float* As /*[KT*128]*/, float* Ws /*[KT*128]*/)
{
    const int tid = threadIdx.x;
    const int tx = tid & 15;
    const int ty = tid >> 4;
    const int m0 = blockIdx.y * 128;
    const int n0 = blockIdx.x * 128;

    u64 c2[4][8];
#pragma unroll
    for (int i = 0; i < 4; i++)
#pragma unroll
        for (int j = 0; j < 8; j++) c2[i][j] = 0ull;

    const int ar = tid >> 1;      // A row 0..127
    const int ah = tid & 1;       // A k-half (8 floats)
    const int wk = tid >> 5;      // W k-row 0..7 (and +8)
    const int wc = tid & 31;      // W col chunk (float4)

    float4 a0, a1, w0, w1;

    // prefetch tile k0 = 0
    {
        a0 = make_float4(0.f, 0.f, 0.f, 0.f); a1 = a0;
        if (m0 + ar < Mrows) {
            const float* Ap = A + (size_t)(m0 + ar) * Dd + ah * 8;
            a0 = *(const float4*)Ap;
            a1 = *(const float4*)(Ap + 4);
        }
        const float* Wp = W + (size_t)wk * Dd + n0 + wc * 4;
        w0 = *(const float4*)Wp;
        w1 = *(const float4*)(Wp + 8 * Dd);
    }

    for (int k0 = 0; k0 < Dd; k0 += KT) {
        __syncthreads();
        As[(ah * 8 + 0) * 128 + ar] = a0.x; As[(ah * 8 + 1) * 128 + ar] = a0.y;
        As[(ah * 8 + 2) * 128 + ar] = a0.z; As[(ah * 8 + 3) * 128 + ar] = a0.w;
        As[(ah * 8 + 4) * 128 + ar] = a1.x; As[(ah * 8 + 5) * 128 + ar] = a1.y;
        As[(ah * 8 + 6) * 128 + ar] = a1.z; As[(ah * 8 + 7) * 128 + ar] = a1.w;
        *(float4*)&Ws[wk * 128 + wc * 4]       = w0;
        *(float4*)&Ws[(wk + 8) * 128 + wc * 4] = w1;
        __syncthreads();

        if (k0 + KT < Dd) {
            a0 = make_float4(0.f, 0.f, 0.f, 0.f); a1 = a0;
            if (m0 + ar < Mrows) {
                const float* Ap = A + (size_t)(m0 + ar) * Dd + (k0 + KT) + ah * 8;
                a0 = *(const float4*)Ap;
                a1 = *(const float4*)(Ap + 4);
            }
            const float* Wp = W + (size_t)(k0 + KT + wk) * Dd + n0 + wc * 4;
            w0 = *(const float4*)Wp;
            w1 = *(const float4*)(Wp + 8 * Dd);
        }

#pragma unroll
        for (int kk = 0; kk < KT; kk++) {
            const float* Ak = As + kk * 128;
            const float* Wr = Ws + kk * 128;
            u64 ap[4];
            ap[0] = *(const u64*)&Ak[ty * 4];
            ap[1] = *(const u64*)&Ak[ty * 4 + 2];
            ap[2] = *(const u64*)&Ak[64 + ty * 4];
            ap[3] = *(const u64*)&Ak[64 + ty * 4 + 2];
            float4 bv0 = *(const float4*)&Wr[tx * 4];
            float4 bv1 = *(const float4*)&Wr[64 + tx * 4];
            u64 bd[8];
            bd[0] = pk2(bv0.x, bv0.x); bd[1] = pk2(bv0.y, bv0.y);
            bd[2] = pk2(bv0.z, bv0.z); bd[3] = pk2(bv0.w, bv0.w);
            bd[4] = pk2(bv1.x, bv1.x); bd[5] = pk2(bv1.y, bv1.y);
            bd[6] = pk2(bv1.z, bv1.z); bd[7] = pk2(bv1.w, bv1.w);
#pragma unroll
            for (int i = 0; i < 4; i++)
#pragma unroll
                for (int j = 0; j < 8; j++) ffma2(c2[i][j], ap[i], bd[j]);
        }
    }

    // epilogue: pair i covers rows {base, base+1}
#pragma unroll
    for (int i = 0; i < 4; i++) {
        int rbase = m0 + ((i < 2) ? (ty * 4 + i * 2) : (64 + ty * 4 + (i - 2) * 2));
#pragma unroll
        for (int j = 0; j < 8; j++) {
            int cidx = n0 + ((j < 4) ? (tx * 4 + j) : (64 + tx * 4 + (j - 4)));
            float2 f = upk2(c2[i][j]);
            float bia = bias[cidx];
            f.x += bia; f.y += bia;
#pragma unroll
            for (int s = 0; s < 2; s++) {
                int r = rbase + s;
                if (r >= Mrows) continue;
                float v = s ? f.y : f.x;
                if (mode == 0) {
                    int bi = r / Tt, t = r - (r / Tt) * Tt;
                    int h = cidx >> 6, dk = cidx & 63;
                    out[(((size_t)(bi * Hh + h)) * Tt + t) * DKk + dk] = v;
                } else {
                    out[(size_t)r * Dd + cidx] = v;
                }
            }
        }
    }
}

__global__ void __launch_bounds__(256, 2) qkv_kernel(
    const float* __restrict__ x,
    const float* __restrict__ Wq, const float* __restrict__ Wk2, const float* __restrict__ Wv,
    const float* __restrict__ bq, const float* __restrict__ bk2, const float* __restrict__ bv,
    float* __restrict__ q, float* __restrict__ k, float* __restrict__ v)
{
    __shared__ float As[KT * 128];
    __shared__ float Ws[KT * 128];
    int z = blockIdx.z;
    const float* W = (z == 0) ? Wq : (z == 1) ? Wk2 : Wv;
    const float* bia = (z == 0) ? bq : (z == 1) ? bk2 : bv;
    float* out = (z == 0) ? q : (z == 1) ? k : v;
    gemm_core(x, W, bia, out, 0, As, Ws);
}

__global__ void __launch_bounds__(256, 2) oproj_kernel(
    const float* __restrict__ ctx, const float* __restrict__ Wo,
    const float* __restrict__ bo, float* __restrict__ out)
{
    __shared__ float As[KT * 128];
    __shared__ float Ws[KT * 128];
    gemm_core(ctx, Wo, bo, out, 1, As, Ws);
}

// ---------------------------------------------------------------------------
// Attention v3 (R3, kept): per (b,h) CTA, 512 threads, 4 rows per warp.
// K/V smem: word = j*64 + ((c + 2j) & 63) -> conflict-free LDS.64.
// P row-interleaved Pg[j][4] (one LDS.128 broadcast serves 4 rows).
// ---------------------------------------------------------------------------
#define NW 16
#define ATTN_SMEM ((2 * Tt * 64 + NW * 800) * 4)

__global__ void __launch_bounds__(32 * NW) attn3_kernel(
    const float* __restrict__ Q, const float* __restrict__ K,
    const float* __restrict__ V, float* __restrict__ ctx)
{
    extern __shared__ float sm[];
    float* Ks = sm;
    float* Vs = sm + Tt * 64;
    const int tid  = threadIdx.x;
    const int lane = tid & 31;
    const int w    = tid >> 5;
    float* Pg = sm + 2 * Tt * 64 + w * 800;

    const int bh = blockIdx.x;
    const int b  = bh / Hh;
    const int h  = bh - b * Hh;

    const float* Kb = K + (size_t)bh * Tt * DKk;
    const float* Vb = V + (size_t)bh * Tt * DKk;
    const float* Qb = Q + (size_t)bh * Tt * DKk;

    for (int e = tid; e < Tt * 32; e += 32 * NW) {
        int j = e >> 5, p = e & 31, c = 2 * p;
        int off = j * 64 + ((c + 2 * j) & 63);
        *(float2*)&Ks[off] = *(const float2*)&Kb[j * 64 + c];
        *(float2*)&Vs[off] = *(const float2*)&Vb[j * 64 + c];
    }
    __syncthreads();

    int jj[7], rot[7];
#pragma unroll
    for (int u = 0; u < 7; u++) {
        int j = lane + 32 * u;
        jj[u]  = (j > Tt - 1) ? (Tt - 1) : j;
        rot[u] = (2 * jj[u]) & 63;
    }
    const int myc = 2 * lane;

    for (int g = w; g < 50; g += NW) {
        const int r0 = g * 4;
        int rs[4];
#pragma unroll
        for (int s = 0; s < 4; s++) rs[s] = (r0 + s > Tt - 1) ? (Tt - 1) : (r0 + s);

        u64 acc[4][7];
#pragma unroll
        for (int s = 0; s < 4; s++)
#pragma unroll
            for (int u = 0; u < 7; u++) acc[s][u] = 0ull;

#pragma unroll
        for (int dc = 0; dc < 8; dc++) {
            u64 qp[4][4];
#pragma unroll
            for (int s = 0; s < 4; s++) {
                const float* qs = Qb + rs[s] * DKk + dc * 8;
                float4 qa = *(const float4*)qs;
                float4 qb = *(const float4*)(qs + 4);
                qp[s][0] = pk2(qa.x, qa.y); qp[s][1] = pk2(qa.z, qa.w);
                qp[s][2] = pk2(qb.x, qb.y); qp[s][3] = pk2(qb.z, qb.w);
            }
            const int c0 = dc * 8;
#pragma unroll
            for (int u = 0; u < 7; u++) {
                const float* kr = Ks + jj[u] * 64;
                u64 kp0 = *(const u64*)&kr[(c0 + 0 + rot[u]) & 63];
                u64 kp1 = *(const u64*)&kr[(c0 + 2 + rot[u]) & 63];
                u64 kp2 = *(const u64*)&kr[(c0 + 4 + rot[u]) & 63];
                u64 kp3 = *(const u64*)&kr[(c0 + 6 + rot[u]) & 63];
#pragma unroll
                for (int s = 0; s < 4; s++) {
                    ffma2(acc[s][u], qp[s][0], kp0);
                    ffma2(acc[s][u], qp[s][1], kp1);
                    ffma2(acc[s][u], qp[s][2], kp2);
                    ffma2(acc[s][u], qp[s][3], kp3);
                }
            }
        }

        float iv[4];
#pragma unroll
        for (int s = 0; s < 4; s++) {
            float sc[7];
            float mx = -1e30f;
#pragma unroll
            for (int u = 0; u < 7; u++) {
                float2 f = upk2(acc[s][u]);
                float val = floorf((f.x + f.y) * 0.125f);
                sc[u] = (lane + 32 * u < Tt) ? val : -1e30f;
                mx = fmaxf(mx, sc[u]);
            }
#pragma unroll
            for (int o = 16; o; o >>= 1) mx = fmaxf(mx, __shfl_xor_sync(0xffffffffu, mx, o));
            float sum = 0.f;
#pragma unroll
            for (int u = 0; u < 7; u++) {
                if (lane + 32 * u < Tt) {
                    float p = __expf(sc[u] - mx);
                    Pg[jj[u] * 4 + s] = p;
                    sum += p;
                }
            }
#pragma unroll
            for (int o = 16; o; o >>= 1) sum += __shfl_xor_sync(0xffffffffu, sum, o);
            iv[s] = 1.f / sum;
        }
        __syncwarp();

        u64 a[4] = {0ull, 0ull, 0ull, 0ull};
        for (int j = 0; j < Tt - 1; j += 2) {
            u64 v0 = *(const u64*)&Vs[j * 64 + ((myc + 2 * j) & 63)];
            u64 v1 = *(const u64*)&Vs[(j + 1) * 64 + ((myc + 2 * j + 2) & 63)];
            float4 pa = *(const float4*)&Pg[j * 4];
            float4 pb = *(const float4*)&Pg[j * 4 + 4];
            ffma2(a[0], pk2(pa.x, pa.x), v0); ffma2(a[0], pk2(pb.x, pb.x), v1);
            ffma2(a[1], pk2(pa.y, pa.y), v0); ffma2(a[1], pk2(pb.y, pb.y), v1);
            ffma2(a[2], pk2(pa.z, pa.z), v0); ffma2(a[2], pk2(pb.z, pb.z), v1);
            ffma2(a[3], pk2(pa.w, pa.w), v0); ffma2(a[3], pk2(pb.w, pb.w), v1);
        }
        {
            int j = Tt - 1;
            u64 v0 = *(const u64*)&Vs[j * 64 + ((myc + 2 * j) & 63)];
            float4 pa = *(const float4*)&Pg[j * 4];
            ffma2(a[0], pk2(pa.x, pa.x), v0);
            ffma2(a[1], pk2(pa.y, pa.y), v0);
            ffma2(a[2], pk2(pa.z, pa.z), v0);
            ffma2(a[3], pk2(pa.w, pa.w), v0);
        }

#pragma unroll
        for (int s = 0; s < 4; s++) {
            float2 o = upk2(a[s]);
            o.x *= iv[s]; o.y *= iv[s];
            *(float2*)&ctx[((size_t)(b * Tt + rs[s])) * Dd + h * DKk + myc] = o;
        }
        __syncwarp();
    }
}

// ---------------------------------------------------------------------------
extern "C" void kernel_launch(void* const* d_in, const int* in_sizes, int n_in,
                              void* d_out, int out_size)
{
    const float* x  = (const float*)d_in[0];
    const float* Wq = (const float*)d_in[1];
    const float* bq = (const float*)d_in[2];
    const float* Wk = (const float*)d_in[3];
    const float* bk = (const float*)d_in[4];
    const float* Wv = (const float*)d_in[5];
    const float* bv = (const float*)d_in[6];
    const float* Wo = (const float*)d_in[7];
    const float* bo = (const float*)d_in[8];
    float* out = (float*)d_out;

    float *q, *k, *v, *ctx;
    cudaGetSymbolAddress((void**)&q,   g_q);
    cudaGetSymbolAddress((void**)&k,   g_k);
    cudaGetSymbolAddress((void**)&v,   g_v);
    cudaGetSymbolAddress((void**)&ctx, g_ctx);

    cudaFuncSetAttribute(attn3_kernel,
                         cudaFuncAttributeMaxDynamicSharedMemorySize, ATTN_SMEM);

    dim3 gridQKV(Dd / 128, (Mrows + 127) / 128, 3);   // 6 x 99 x 3
    qkv_kernel<<<gridQKV, 256>>>(x, Wq, Wk, Wv, bq, bk, bv, q, k, v);

    attn3_kernel<<<Bc * Hh, 32 * NW, ATTN_SMEM>>>(q, k, v, ctx);

    dim3 gridO(Dd / 128, (Mrows + 127) / 128, 1);
    oproj_kernel<<<gridO, 256>>>(ctx, Wo, bo, out);
}